// round 2
// baseline (speedup 1.0000x reference)
#include <cuda_runtime.h>

#define NS 8192
#define NH 64
#define CC 64

// Scratch (allocation-free rule: __device__ globals)
__device__ float g_X1[NS * CC];
__device__ float g_X2[NS * CC];

// Kernel 1: per-s reductions over the 64x64 H_prime tile.
//   t[h]    = sum_c Hp[s][c][h] * w1[c]
//   X2[s,c] = sum_h Hp[s][c][h] * w3[h]
//   X1[s,c']= sum_h t[h] * W2_w[c'][h]
__global__ void __launch_bounds__(256) prep_kernel(
    const float* __restrict__ Hp, const float* __restrict__ w1,
    const float* __restrict__ W2, const float* __restrict__ w3)
{
    __shared__ float tile[64 * 65];  // padded: stride 65 kills bank conflicts
    __shared__ float tsm[64];
    const int s = blockIdx.x;
    const int tid = threadIdx.x;
    const float4* base = (const float4*)(Hp + (size_t)s * (CC * NH));

    // Cooperative coalesced load of the 64x64 tile (1024 float4s)
    #pragma unroll
    for (int i = tid; i < 1024; i += 256) {
        float4 v = base[i];
        int g = i * 4;
        int c = g >> 6, h = g & 63;
        float* dst = &tile[c * 65 + h];
        dst[0] = v.x; dst[1] = v.y; dst[2] = v.z; dst[3] = v.w;
    }
    __syncthreads();

    if (tid < 64) {
        const int h = tid;
        float acc = 0.f;
        #pragma unroll
        for (int c = 0; c < 64; c++) acc += tile[c * 65 + h] * w1[c];
        tsm[h] = acc;
    } else if (tid < 128) {
        const int c = tid - 64;
        float acc = 0.f;
        #pragma unroll
        for (int h = 0; h < 64; h++) acc += tile[c * 65 + h] * w3[h];
        g_X2[(size_t)s * CC + c] = acc;
    }
    __syncthreads();

    if (tid < 64) {
        const int cp = tid;
        const float* wr = W2 + cp * NH;
        float acc = 0.f;
        #pragma unroll
        for (int h = 0; h < 64; h++) acc += tsm[h] * wr[h];
        g_X1[(size_t)s * CC + cp] = acc;
    }
}

// Kernel 2: one CTA per row s. Exploit ~1% mask density:
// only compute dot(X1[s], X2[j]) / read V,B where mask != 0.
// Keep the whole row's e-values in registers (16 per thread),
// block-reduce the sum, scale, single coalesced write.
// Mask is read as 4-byte words (harness marshals the JAX bool as a
// 32-bit type); nonzero bits <=> true for float32 1.0f / int32 1.
__global__ void __launch_bounds__(512) row_kernel(
    const float* __restrict__ V, const float* __restrict__ B,
    const unsigned int* __restrict__ mask, float* __restrict__ out)
{
    const int s = blockIdx.x;
    const int tid = threadIdx.x;
    __shared__ float x1s[64];
    __shared__ float wsum[16];

    if (tid < 64) x1s[tid] = g_X1[(size_t)s * CC + tid];
    __syncthreads();

    const size_t rowoff = (size_t)s * NS;
    float e[16];
    float lsum = 0.f;

    #pragma unroll
    for (int it = 0; it < 16; it++) {
        const int j = tid + it * 512;
        const unsigned int m = mask[rowoff + j];
        float ev = 0.f;
        if (m != 0u) {
            const float4* x2p = (const float4*)(g_X2 + (size_t)j * CC);
            const float4* x1p = (const float4*)x1s;
            float dot = 0.f;
            #pragma unroll
            for (int q = 0; q < 16; q++) {
                float4 a = __ldg(&x2p[q]);
                float4 b = x1p[q];
                dot += a.x * b.x + a.y * b.y + a.z * b.z + a.w * b.w;
            }
            const float bb = B[rowoff + j];
            const float vv = V[rowoff + j];
            const float sg = 1.f / (1.f + expf(-(dot + bb)));
            ev = expf(vv * sg);
        }
        e[it] = ev;
        lsum += ev;
    }

    // Block reduction over 16 warps
    #pragma unroll
    for (int o = 16; o; o >>= 1) lsum += __shfl_down_sync(0xffffffffu, lsum, o);
    if ((tid & 31) == 0) wsum[tid >> 5] = lsum;
    __syncthreads();
    if (tid < 32) {
        float w = (tid < 16) ? wsum[tid] : 0.f;
        #pragma unroll
        for (int o = 8; o; o >>= 1) w += __shfl_down_sync(0xffffffffu, w, o);
        if (tid == 0) wsum[0] = w;
    }
    __syncthreads();

    const float inv = 1.f / (wsum[0] + 1e-6f);
    #pragma unroll
    for (int it = 0; it < 16; it++)
        out[rowoff + tid + it * 512] = e[it] * inv;
}

extern "C" void kernel_launch(void* const* d_in, const int* in_sizes, int n_in,
                              void* d_out, int out_size)
{
    (void)in_sizes; (void)n_in; (void)out_size;
    const float* Hp  = (const float*)d_in[0];
    const float* w1  = (const float*)d_in[1];
    const float* W2  = (const float*)d_in[2];
    const float* w3  = (const float*)d_in[3];
    const float* V   = (const float*)d_in[4];
    const float* B   = (const float*)d_in[5];
    const unsigned int* mask = (const unsigned int*)d_in[6];
    float* out = (float*)d_out;

    prep_kernel<<<NS, 256>>>(Hp, w1, W2, w3);
    row_kernel<<<NS, 512>>>(V, B, mask, out);
}

// round 3
// speedup vs baseline: 2.2661x; 2.2661x over previous
#include <cuda_runtime.h>

#define NS 8192
#define NH 64
#define CC 64

// Scratch (allocation-free rule: __device__ globals)
__device__ float g_X1[NS * CC];
__device__ float g_X2[NS * CC];

// ---------------------------------------------------------------------------
// Kernel 1: per-s reductions over the 64x64 H_prime tile. 64 threads/CTA,
// every thread busy in every phase. Phases 1+2 fused for ILP.
//   t[h]     = sum_c Hp[s][c][h] * w1[c]
//   X2[s,c]  = sum_h Hp[s][c][h] * w3[h]
//   X1[s,c'] = sum_h t[h] * W2_w[c'][h]
// ---------------------------------------------------------------------------
__global__ void __launch_bounds__(64) prep_kernel(
    const float* __restrict__ Hp, const float* __restrict__ w1,
    const float* __restrict__ W2, const float* __restrict__ w3)
{
    __shared__ float tile[64 * 65];   // stride 65: conflict-free both ways
    __shared__ float tsm[64];
    __shared__ float w1s[64], w3s[64];

    const int s   = blockIdx.x;
    const int tid = threadIdx.x;     // 0..63

    w1s[tid] = w1[tid];
    w3s[tid] = w3[tid];

    // Coalesced tile load: 1024 float4 / 64 threads = 16 each, front-batched
    const float4* base = (const float4*)(Hp + (size_t)s * (CC * NH));
    #pragma unroll
    for (int k = 0; k < 16; k++) {
        int i = tid + k * 64;
        float4 v = base[i];
        int g = i * 4;
        int c = g >> 6, h = g & 63;
        float* dst = &tile[c * 65 + h];
        dst[0] = v.x; dst[1] = v.y; dst[2] = v.z; dst[3] = v.w;
    }
    __syncthreads();

    // Fused phase: thread computes t[tid] (reduce over c) and X2[s,tid]
    // (reduce over h) in one loop — two independent accumulators.
    float acc_t = 0.f, acc_x2 = 0.f;
    #pragma unroll
    for (int k = 0; k < 64; k++) {
        acc_t  += tile[k * 65 + tid] * w1s[k];   // varying c, fixed h=tid
        acc_x2 += tile[tid * 65 + k] * w3s[k];   // fixed c=tid, varying h
    }
    tsm[tid] = acc_t;
    g_X2[(size_t)s * CC + tid] = acc_x2;
    __syncthreads();

    // X1[s,tid] = sum_h tsm[h] * W2[tid*64 + h]  (W2 is 16KB, L1-resident)
    const float* wr = W2 + tid * NH;
    float acc = 0.f;
    #pragma unroll
    for (int h = 0; h < 64; h++) acc += tsm[h] * __ldg(&wr[h]);
    g_X1[(size_t)s * CC + tid] = acc;
}

// ---------------------------------------------------------------------------
// Kernel 2: one CTA (512 thr) per row s. Compact masked columns, then
// warp-per-element cooperative dot (full lane efficiency, coalesced X2).
// ---------------------------------------------------------------------------
#define MAXM 2048   // binomial(8192, 0.01): mean 82, std 9 — 2048 is >200 sigma

__global__ void __launch_bounds__(512) row_kernel(
    const float* __restrict__ V, const float* __restrict__ B,
    const unsigned int* __restrict__ mask, float* __restrict__ out)
{
    __shared__ float e_sm[NS];      // 32 KB row buffer
    __shared__ int   idxs[MAXM];    // 8 KB compacted column indices
    __shared__ float x1s[64];
    __shared__ float wsum[16];
    __shared__ int   cnt;

    const int s    = blockIdx.x;
    const int tid  = threadIdx.x;
    const int lane = tid & 31;
    const int wid  = tid >> 5;
    const size_t rowoff = (size_t)s * NS;

    if (tid == 0) cnt = 0;
    if (tid < 64) x1s[tid] = g_X1[(size_t)s * CC + tid];
    #pragma unroll
    for (int k = 0; k < 16; k++) e_sm[tid + k * 512] = 0.f;
    __syncthreads();

    // --- Phase A: vectorized mask scan + compaction -----------------------
    const uint4* mv = (const uint4*)(mask + rowoff);
    #pragma unroll
    for (int k = 0; k < 4; k++) {
        int vi = tid + k * 512;
        uint4 u = mv[vi];          // 4 independent LDG.128 per thread
        if (u.x | u.y | u.z | u.w) {
            int bj = vi * 4;
            if (u.x) { int p = atomicAdd(&cnt, 1); idxs[p] = bj;     }
            if (u.y) { int p = atomicAdd(&cnt, 1); idxs[p] = bj + 1; }
            if (u.z) { int p = atomicAdd(&cnt, 1); idxs[p] = bj + 2; }
            if (u.w) { int p = atomicAdd(&cnt, 1); idxs[p] = bj + 3; }
        }
    }
    __syncthreads();
    const int m = cnt;

    // --- Phase B: warp-per-element cooperative processing -----------------
    const float x1a = x1s[lane];
    const float x1b = x1s[lane + 32];
    float lsum = 0.f;

    for (int el = wid; el < m; el += 16) {
        const int j = idxs[el];
        const float bb = __ldg(B + rowoff + j);     // broadcast (same addr)
        const float vv = __ldg(V + rowoff + j);
        const float* x2 = g_X2 + (size_t)j * CC;
        float p = __ldg(x2 + lane) * x1a + __ldg(x2 + lane + 32) * x1b;
        #pragma unroll
        for (int o = 16; o; o >>= 1) p += __shfl_xor_sync(0xffffffffu, p, o);
        if (lane == 0) {
            const float sg = 1.f / (1.f + expf(-(p + bb)));
            const float ev = expf(vv * sg);
            e_sm[j] = ev;
            lsum += ev;
        }
    }

    // --- Block reduction of row sum ---------------------------------------
    #pragma unroll
    for (int o = 16; o; o >>= 1) lsum += __shfl_down_sync(0xffffffffu, lsum, o);
    if (lane == 0) wsum[wid] = lsum;
    __syncthreads();
    if (tid < 32) {
        float w = (tid < 16) ? wsum[tid] : 0.f;
        #pragma unroll
        for (int o = 8; o; o >>= 1) w += __shfl_down_sync(0xffffffffu, w, o);
        if (tid == 0) wsum[0] = w;
    }
    __syncthreads();

    // --- Scaled coalesced write -------------------------------------------
    const float inv = 1.f / (wsum[0] + 1e-6f);
    #pragma unroll
    for (int k = 0; k < 16; k++) {
        int j = tid + k * 512;
        out[rowoff + j] = e_sm[j] * inv;
    }
}

extern "C" void kernel_launch(void* const* d_in, const int* in_sizes, int n_in,
                              void* d_out, int out_size)
{
    (void)in_sizes; (void)n_in; (void)out_size;
    const float* Hp  = (const float*)d_in[0];
    const float* w1  = (const float*)d_in[1];
    const float* W2  = (const float*)d_in[2];
    const float* w3  = (const float*)d_in[3];
    const float* V   = (const float*)d_in[4];
    const float* B   = (const float*)d_in[5];
    const unsigned int* mask = (const unsigned int*)d_in[6];
    float* out = (float*)d_out;

    prep_kernel<<<NS, 64>>>(Hp, w1, W2, w3);
    row_kernel<<<NS, 512>>>(V, B, mask, out);
}

// round 4
// speedup vs baseline: 3.2343x; 1.4272x over previous
#include <cuda_runtime.h>

#define NS 8192
#define NH 64
#define CC 64

// Scratch (allocation-free rule: __device__ globals)
__device__ float g_X1[NS * CC];
__device__ float g_X2[NS * CC];

// ---------------------------------------------------------------------------
// Kernel 1: per-s reductions over the 64x64 H_prime tile. 256 threads/CTA,
// no smem tile: float4 split i = tid + 256k gives each thread a FIXED h-quad
// (h0 = (tid&15)*4) and c = tid>>4 + 16k, so both reductions run on register
// partials + warp shuffles.
//   t[h]     = sum_c Hp[s][c][h] * w1[c]
//   X2[s,c]  = sum_h Hp[s][c][h] * w3[h]
//   X1[s,c'] = sum_h t[h] * W2_w[c'][h]
// ---------------------------------------------------------------------------
__global__ void __launch_bounds__(256) prep_kernel(
    const float* __restrict__ Hp, const float* __restrict__ w1,
    const float* __restrict__ W2, const float* __restrict__ w3)
{
    __shared__ float t_sm[64];
    const int s    = blockIdx.x;
    const int tid  = threadIdx.x;
    const int lane = tid & 31;

    if (tid < 64) t_sm[tid] = 0.f;

    // Front-batched streaming load: 4 float4 per thread (MLP 4 x 8 warps)
    const float4* base = (const float4*)(Hp + (size_t)s * (CC * NH));
    float4 v[4];
    #pragma unroll
    for (int k = 0; k < 4; k++) v[k] = base[tid + 256 * k];

    const int h0 = (tid & 15) * 4;
    const int c0 = tid >> 4;
    float w3v0 = __ldg(w3 + h0),     w3v1 = __ldg(w3 + h0 + 1);
    float w3v2 = __ldg(w3 + h0 + 2), w3v3 = __ldg(w3 + h0 + 3);

    __syncthreads();   // t_sm init visible before atomics below

    float tq0 = 0.f, tq1 = 0.f, tq2 = 0.f, tq3 = 0.f;
    #pragma unroll
    for (int k = 0; k < 4; k++) {
        const int c = c0 + 16 * k;
        const float w1c = __ldg(w1 + c);            // half-warp broadcast
        tq0 += v[k].x * w1c;  tq1 += v[k].y * w1c;
        tq2 += v[k].z * w1c;  tq3 += v[k].w * w1c;

        // X2[c] partial: dot4 with w3, reduce across the 16-lane half that
        // shares c (shfl_xor offsets < 16 stay within the half).
        float d = v[k].x * w3v0 + v[k].y * w3v1 + v[k].z * w3v2 + v[k].w * w3v3;
        #pragma unroll
        for (int o = 8; o; o >>= 1) d += __shfl_xor_sync(0xffffffffu, d, o);
        if ((lane & 15) == 0)
            g_X2[(size_t)s * CC + c] = d;   // unique c per (warp, half, k)
    }

    // t[h0..h0+3]: lanes l and l+16 share the h-quad -> pair-combine, then
    // 8-warp accumulate via spread-address smem atomics (conflict-free).
    tq0 += __shfl_xor_sync(0xffffffffu, tq0, 16);
    tq1 += __shfl_xor_sync(0xffffffffu, tq1, 16);
    tq2 += __shfl_xor_sync(0xffffffffu, tq2, 16);
    tq3 += __shfl_xor_sync(0xffffffffu, tq3, 16);
    if (lane < 16) {
        atomicAdd(&t_sm[h0],     tq0);
        atomicAdd(&t_sm[h0 + 1], tq1);
        atomicAdd(&t_sm[h0 + 2], tq2);
        atomicAdd(&t_sm[h0 + 3], tq3);
    }
    __syncthreads();

    // X1[c'] = sum_h t[h] * W2[c'][h] : 4 lanes per c', 16 h each.
    const int cp   = tid >> 2;      // 0..63
    const int part = tid & 3;
    const float4* w2v = (const float4*)(W2 + cp * NH + part * 16);
    const float*  tp  = t_sm + part * 16;
    float acc = 0.f;
    #pragma unroll
    for (int j = 0; j < 4; j++) {
        float4 w = __ldg(&w2v[j]);
        acc += w.x * tp[4*j] + w.y * tp[4*j+1] + w.z * tp[4*j+2] + w.w * tp[4*j+3];
    }
    acc += __shfl_xor_sync(0xffffffffu, acc, 1);
    acc += __shfl_xor_sync(0xffffffffu, acc, 2);
    if (part == 0) g_X1[(size_t)s * CC + cp] = acc;
}

// ---------------------------------------------------------------------------
// Kernel 2: one CTA (512 thr) per row s. Compact masked columns, then
// warp-per-element cooperative dot; vectorized (float4) init + final write.
// ---------------------------------------------------------------------------
#define MAXM 2048   // binomial(8192, 0.01): mean 82, std 9 — huge margin

__global__ void __launch_bounds__(512) row_kernel(
    const float* __restrict__ V, const float* __restrict__ B,
    const unsigned int* __restrict__ mask, float* __restrict__ out)
{
    __shared__ float e_sm[NS];      // 32 KB row buffer
    __shared__ int   idxs[MAXM];    // 8 KB compacted column indices
    __shared__ float x1s[64];
    __shared__ float wsum[16];
    __shared__ int   cnt;

    const int s    = blockIdx.x;
    const int tid  = threadIdx.x;
    const int lane = tid & 31;
    const int wid  = tid >> 5;
    const size_t rowoff = (size_t)s * NS;

    if (tid == 0) cnt = 0;
    if (tid < 64) x1s[tid] = g_X1[(size_t)s * CC + tid];

    float4* e4 = (float4*)e_sm;
    const float4 z4 = make_float4(0.f, 0.f, 0.f, 0.f);
    #pragma unroll
    for (int k = 0; k < 4; k++) e4[tid + k * 512] = z4;
    __syncthreads();

    // --- Phase A: vectorized mask scan + compaction -----------------------
    const uint4* mv = (const uint4*)(mask + rowoff);
    #pragma unroll
    for (int k = 0; k < 4; k++) {
        int vi = tid + k * 512;
        uint4 u = mv[vi];          // 4 independent LDG.128 per thread
        if (u.x | u.y | u.z | u.w) {
            int bj = vi * 4;
            if (u.x) { int p = atomicAdd(&cnt, 1); idxs[p] = bj;     }
            if (u.y) { int p = atomicAdd(&cnt, 1); idxs[p] = bj + 1; }
            if (u.z) { int p = atomicAdd(&cnt, 1); idxs[p] = bj + 2; }
            if (u.w) { int p = atomicAdd(&cnt, 1); idxs[p] = bj + 3; }
        }
    }
    __syncthreads();
    const int m = cnt;

    // --- Phase B: warp-per-element cooperative processing -----------------
    const float x1a = x1s[lane];
    const float x1b = x1s[lane + 32];
    float lsum = 0.f;

    for (int el = wid; el < m; el += 16) {
        const int j = idxs[el];
        const float bb = __ldg(B + rowoff + j);     // broadcast (same addr)
        const float vv = __ldg(V + rowoff + j);
        const float* x2 = g_X2 + (size_t)j * CC;
        float p = __ldg(x2 + lane) * x1a + __ldg(x2 + lane + 32) * x1b;
        #pragma unroll
        for (int o = 16; o; o >>= 1) p += __shfl_xor_sync(0xffffffffu, p, o);
        if (lane == 0) {
            const float sg = 1.f / (1.f + expf(-(p + bb)));
            const float ev = expf(vv * sg);
            e_sm[j] = ev;
            lsum += ev;
        }
    }

    // --- Block reduction of row sum ---------------------------------------
    #pragma unroll
    for (int o = 16; o; o >>= 1) lsum += __shfl_down_sync(0xffffffffu, lsum, o);
    if (lane == 0) wsum[wid] = lsum;
    __syncthreads();
    if (tid < 32) {
        float w = (tid < 16) ? wsum[tid] : 0.f;
        #pragma unroll
        for (int o = 8; o; o >>= 1) w += __shfl_down_sync(0xffffffffu, w, o);
        if (tid == 0) wsum[0] = w;
    }
    __syncthreads();

    // --- Scaled vectorized write ------------------------------------------
    const float inv = 1.f / (wsum[0] + 1e-6f);
    float4* out4 = (float4*)(out + rowoff);
    #pragma unroll
    for (int k = 0; k < 4; k++) {
        float4 e = e4[tid + k * 512];
        e.x *= inv; e.y *= inv; e.z *= inv; e.w *= inv;
        out4[tid + k * 512] = e;
    }
}

extern "C" void kernel_launch(void* const* d_in, const int* in_sizes, int n_in,
                              void* d_out, int out_size)
{
    (void)in_sizes; (void)n_in; (void)out_size;
    const float* Hp  = (const float*)d_in[0];
    const float* w1  = (const float*)d_in[1];
    const float* W2  = (const float*)d_in[2];
    const float* w3  = (const float*)d_in[3];
    const float* V   = (const float*)d_in[4];
    const float* B   = (const float*)d_in[5];
    const unsigned int* mask = (const unsigned int*)d_in[6];
    float* out = (float*)d_out;

    prep_kernel<<<NS, 256>>>(Hp, w1, W2, w3);
    row_kernel<<<NS, 512>>>(V, B, mask, out);
}

// round 5
// speedup vs baseline: 3.6593x; 1.1314x over previous
#include <cuda_runtime.h>

#define NS 8192
#define NH 64
#define CC 64

// Scratch (allocation-free rule: __device__ globals)
__device__ float g_X1[NS * CC];
__device__ float g_X2[NS * CC];

// ---------------------------------------------------------------------------
// Kernel 1: per-s reductions over the 64x64 H_prime tile. 256 threads/CTA,
// register-resident: float4 split i = tid + 256k gives each thread a FIXED
// h-quad (h0 = (tid&15)*4) and c = tid>>4 + 16k.
// ---------------------------------------------------------------------------
__global__ void __launch_bounds__(256) prep_kernel(
    const float* __restrict__ Hp, const float* __restrict__ w1,
    const float* __restrict__ W2, const float* __restrict__ w3)
{
    __shared__ float t_sm[64];
    const int s    = blockIdx.x;
    const int tid  = threadIdx.x;
    const int lane = tid & 31;

    if (tid < 64) t_sm[tid] = 0.f;

    // Front-batched streaming load: 4 float4 per thread
    const float4* base = (const float4*)(Hp + (size_t)s * (CC * NH));
    float4 v[4];
    #pragma unroll
    for (int k = 0; k < 4; k++) v[k] = base[tid + 256 * k];

    const int h0 = (tid & 15) * 4;
    const int c0 = tid >> 4;
    float w3v0 = __ldg(w3 + h0),     w3v1 = __ldg(w3 + h0 + 1);
    float w3v2 = __ldg(w3 + h0 + 2), w3v3 = __ldg(w3 + h0 + 3);

    __syncthreads();   // t_sm init visible before atomics below

    float tq0 = 0.f, tq1 = 0.f, tq2 = 0.f, tq3 = 0.f;
    #pragma unroll
    for (int k = 0; k < 4; k++) {
        const int c = c0 + 16 * k;
        const float w1c = __ldg(w1 + c);
        tq0 += v[k].x * w1c;  tq1 += v[k].y * w1c;
        tq2 += v[k].z * w1c;  tq3 += v[k].w * w1c;

        // X2[c]: dot4 with w3, reduce across the 16-lane half sharing c
        float d = v[k].x * w3v0 + v[k].y * w3v1 + v[k].z * w3v2 + v[k].w * w3v3;
        #pragma unroll
        for (int o = 8; o; o >>= 1) d += __shfl_xor_sync(0xffffffffu, d, o);
        if ((lane & 15) == 0)
            g_X2[(size_t)s * CC + c] = d;
    }

    // t[h0..h0+3]: pair-combine lanes l / l+16, then smem atomics (spread)
    tq0 += __shfl_xor_sync(0xffffffffu, tq0, 16);
    tq1 += __shfl_xor_sync(0xffffffffu, tq1, 16);
    tq2 += __shfl_xor_sync(0xffffffffu, tq2, 16);
    tq3 += __shfl_xor_sync(0xffffffffu, tq3, 16);
    if (lane < 16) {
        atomicAdd(&t_sm[h0],     tq0);
        atomicAdd(&t_sm[h0 + 1], tq1);
        atomicAdd(&t_sm[h0 + 2], tq2);
        atomicAdd(&t_sm[h0 + 3], tq3);
    }
    __syncthreads();

    // X1[c'] = sum_h t[h] * W2[c'][h] : 4 lanes per c'
    const int cp   = tid >> 2;
    const int part = tid & 3;
    const float4* w2v = (const float4*)(W2 + cp * NH + part * 16);
    const float*  tp  = t_sm + part * 16;
    float acc = 0.f;
    #pragma unroll
    for (int j = 0; j < 4; j++) {
        float4 w = __ldg(&w2v[j]);
        acc += w.x * tp[4*j] + w.y * tp[4*j+1] + w.z * tp[4*j+2] + w.w * tp[4*j+3];
    }
    acc += __shfl_xor_sync(0xffffffffu, acc, 1);
    acc += __shfl_xor_sync(0xffffffffu, acc, 2);
    if (part == 0) g_X1[(size_t)s * CC + cp] = acc;
}

// ---------------------------------------------------------------------------
// Kernel 2: one CTA (512 thr) per row s.
//  - front-batch mask loads into registers
//  - zero-write the whole output row EARLY (overlaps all later latency)
//  - compact masked columns, warp-per-element cooperative dot
//  - compact e buffer (~82 entries), scatter e*inv over the zeros at the end
// ---------------------------------------------------------------------------
#define MAXM 2048   // binomial(8192, 0.01): mean 82, std 9 — huge margin

__global__ void __launch_bounds__(512) row_kernel(
    const float* __restrict__ V, const float* __restrict__ B,
    const unsigned int* __restrict__ mask, float* __restrict__ out)
{
    __shared__ int   idxs[MAXM];    // 8 KB compacted column indices
    __shared__ float e_c[MAXM];     // 8 KB compacted e values
    __shared__ float x1s[64];
    __shared__ float wsum[16];
    __shared__ int   cnt;

    const int s    = blockIdx.x;
    const int tid  = threadIdx.x;
    const int lane = tid & 31;
    const int wid  = tid >> 5;
    const size_t rowoff = (size_t)s * NS;

    if (tid == 0) cnt = 0;
    if (tid < 64) x1s[tid] = g_X1[(size_t)s * CC + tid];

    // Front-batch the mask loads (phase A depends on them)
    const uint4* mv = (const uint4*)(mask + rowoff);
    uint4 u[4];
    #pragma unroll
    for (int k = 0; k < 4; k++) u[k] = mv[tid + k * 512];

    // Fire-and-forget zero write of the output row — overlaps everything
    float4* out4 = (float4*)(out + rowoff);
    const float4 z4 = make_float4(0.f, 0.f, 0.f, 0.f);
    #pragma unroll
    for (int k = 0; k < 4; k++) out4[tid + k * 512] = z4;

    __syncthreads();   // cnt/x1s visible

    // --- Phase A: compaction ----------------------------------------------
    #pragma unroll
    for (int k = 0; k < 4; k++) {
        if (u[k].x | u[k].y | u[k].z | u[k].w) {
            int bj = (tid + k * 512) * 4;
            if (u[k].x) { int p = atomicAdd(&cnt, 1); idxs[p] = bj;     }
            if (u[k].y) { int p = atomicAdd(&cnt, 1); idxs[p] = bj + 1; }
            if (u[k].z) { int p = atomicAdd(&cnt, 1); idxs[p] = bj + 2; }
            if (u[k].w) { int p = atomicAdd(&cnt, 1); idxs[p] = bj + 3; }
        }
    }
    __syncthreads();
    const int m = cnt;

    // --- Phase B: warp-per-element cooperative processing -----------------
    const float x1a = x1s[lane];
    const float x1b = x1s[lane + 32];
    float lsum = 0.f;

    for (int el = wid; el < m; el += 16) {
        const int j = idxs[el];
        const float bb = __ldg(B + rowoff + j);     // warp broadcast
        const float vv = __ldg(V + rowoff + j);
        const float* x2 = g_X2 + (size_t)j * CC;
        float p = __ldg(x2 + lane) * x1a + __ldg(x2 + lane + 32) * x1b;
        #pragma unroll
        for (int o = 16; o; o >>= 1) p += __shfl_xor_sync(0xffffffffu, p, o);
        if (lane == 0) {
            const float sg = 1.f / (1.f + expf(-(p + bb)));
            const float ev = expf(vv * sg);
            e_c[el] = ev;
            lsum += ev;
        }
    }

    // --- Block reduction of row sum ---------------------------------------
    #pragma unroll
    for (int o = 16; o; o >>= 1) lsum += __shfl_down_sync(0xffffffffu, lsum, o);
    if (lane == 0) wsum[wid] = lsum;
    __syncthreads();
    if (tid < 32) {
        float w = (tid < 16) ? wsum[tid] : 0.f;
        #pragma unroll
        for (int o = 8; o; o >>= 1) w += __shfl_down_sync(0xffffffffu, w, o);
        if (tid == 0) wsum[0] = w;
    }
    __syncthreads();

    // --- Sparse scatter of scaled values over the zeros --------------------
    const float inv = 1.f / (wsum[0] + 1e-6f);
    for (int el = tid; el < m; el += 512)
        out[rowoff + idxs[el]] = e_c[el] * inv;
}

extern "C" void kernel_launch(void* const* d_in, const int* in_sizes, int n_in,
                              void* d_out, int out_size)
{
    (void)in_sizes; (void)n_in; (void)out_size;
    const float* Hp  = (const float*)d_in[0];
    const float* w1  = (const float*)d_in[1];
    const float* W2  = (const float*)d_in[2];
    const float* w3  = (const float*)d_in[3];
    const float* V   = (const float*)d_in[4];
    const float* B   = (const float*)d_in[5];
    const unsigned int* mask = (const unsigned int*)d_in[6];
    float* out = (float*)d_out;

    prep_kernel<<<NS, 256>>>(Hp, w1, W2, w3);
    row_kernel<<<NS, 512>>>(V, B, mask, out);
}

// round 6
// speedup vs baseline: 4.2058x; 1.1493x over previous
#include <cuda_runtime.h>

#define NS 8192
#define NH 64
#define CC 64

// Scratch (allocation-free rule: __device__ globals)
__device__ float g_X1[NS * CC];
__device__ float g_X2[NS * CC];

// ---------------------------------------------------------------------------
// Kernel 1: 2 tiles (s values) per CTA, 256 threads. All 8 float4 loads per
// thread issued up front (MLP=8). Register-resident reductions:
//   i = tid + 256k  ->  fixed h-quad h0=(tid&15)*4, c = tid>>4 + 16k.
// ---------------------------------------------------------------------------
__global__ void __launch_bounds__(256) prep_kernel(
    const float* __restrict__ Hp, const float* __restrict__ w1,
    const float* __restrict__ W2, const float* __restrict__ w3)
{
    __shared__ float t_sm[2][64];
    const int s0   = blockIdx.x * 2;
    const int tid  = threadIdx.x;
    const int lane = tid & 31;

    if (tid < 128) ((float*)t_sm)[tid] = 0.f;

    // Front-batched streaming loads for BOTH tiles (read-once: evict-first)
    const float4* base = (const float4*)(Hp + (size_t)s0 * (CC * NH));
    float4 v[2][4];
    #pragma unroll
    for (int p = 0; p < 2; p++)
        #pragma unroll
        for (int k = 0; k < 4; k++)
            v[p][k] = __ldcs(base + p * 1024 + tid + 256 * k);

    const int h0 = (tid & 15) * 4;
    const int c0 = tid >> 4;
    const float w3v0 = __ldg(w3 + h0),     w3v1 = __ldg(w3 + h0 + 1);
    const float w3v2 = __ldg(w3 + h0 + 2), w3v3 = __ldg(w3 + h0 + 3);
    float w1c[4];
    #pragma unroll
    for (int k = 0; k < 4; k++) w1c[k] = __ldg(w1 + c0 + 16 * k);

    __syncthreads();   // t_sm init visible before atomics

    #pragma unroll
    for (int p = 0; p < 2; p++) {
        float tq0 = 0.f, tq1 = 0.f, tq2 = 0.f, tq3 = 0.f;
        #pragma unroll
        for (int k = 0; k < 4; k++) {
            tq0 += v[p][k].x * w1c[k];  tq1 += v[p][k].y * w1c[k];
            tq2 += v[p][k].z * w1c[k];  tq3 += v[p][k].w * w1c[k];

            // X2[c]: dot4 with w3, reduce across the 16-lane half sharing c
            float d = v[p][k].x * w3v0 + v[p][k].y * w3v1
                    + v[p][k].z * w3v2 + v[p][k].w * w3v3;
            #pragma unroll
            for (int o = 8; o; o >>= 1) d += __shfl_xor_sync(0xffffffffu, d, o);
            if ((lane & 15) == 0)
                g_X2[(size_t)(s0 + p) * CC + c0 + 16 * k] = d;
        }
        // t[h0..h0+3]: pair-combine lanes l / l+16, spread smem atomics
        tq0 += __shfl_xor_sync(0xffffffffu, tq0, 16);
        tq1 += __shfl_xor_sync(0xffffffffu, tq1, 16);
        tq2 += __shfl_xor_sync(0xffffffffu, tq2, 16);
        tq3 += __shfl_xor_sync(0xffffffffu, tq3, 16);
        if (lane < 16) {
            atomicAdd(&t_sm[p][h0],     tq0);
            atomicAdd(&t_sm[p][h0 + 1], tq1);
            atomicAdd(&t_sm[p][h0 + 2], tq2);
            atomicAdd(&t_sm[p][h0 + 3], tq3);
        }
    }
    __syncthreads();

    // X1[c'] = sum_h t[h] * W2[c'][h] : 4 lanes per c', both tiles
    const int cp   = tid >> 2;
    const int part = tid & 3;
    const float4* w2v = (const float4*)(W2 + cp * NH + part * 16);
    float4 w[4];
    #pragma unroll
    for (int j = 0; j < 4; j++) w[j] = __ldg(&w2v[j]);

    #pragma unroll
    for (int p = 0; p < 2; p++) {
        const float* tp = &t_sm[p][part * 16];
        float acc = 0.f;
        #pragma unroll
        for (int j = 0; j < 4; j++)
            acc += w[j].x * tp[4*j] + w[j].y * tp[4*j+1]
                 + w[j].z * tp[4*j+2] + w[j].w * tp[4*j+3];
        acc += __shfl_xor_sync(0xffffffffu, acc, 1);
        acc += __shfl_xor_sync(0xffffffffu, acc, 2);
        if (part == 0) g_X1[(size_t)(s0 + p) * CC + cp] = acc;
    }
}

// ---------------------------------------------------------------------------
// Kernel 2: one CTA (512 thr) per row s.
//  - front-batch mask loads (evict-first), zero-write the row early (streaming)
//  - compact, then HALF-WARP per masked element: float4 X2 loads, 4-shfl reduce
//  - row sum via per-warp smem atomicAdd; sparse scatter of e*inv at the end
// ---------------------------------------------------------------------------
#define MAXM 2048   // binomial(8192, 0.01): mean 82, std 9 — huge margin

__global__ void __launch_bounds__(512) row_kernel(
    const float* __restrict__ V, const float* __restrict__ B,
    const unsigned int* __restrict__ mask, float* __restrict__ out)
{
    __shared__ int   idxs[MAXM];    // 8 KB compacted column indices
    __shared__ float e_c[MAXM];     // 8 KB compacted e values
    __shared__ float x1s[64];
    __shared__ float rowsum;
    __shared__ int   cnt;

    const int s    = blockIdx.x;
    const int tid  = threadIdx.x;
    const int lane = tid & 31;
    const int wid  = tid >> 5;
    const size_t rowoff = (size_t)s * NS;

    if (tid == 0) { cnt = 0; rowsum = 1e-6f; }
    if (tid < 64) x1s[tid] = g_X1[(size_t)s * CC + tid];

    // Front-batch the mask loads (evict-first: read exactly once)
    const uint4* mv = (const uint4*)(mask + rowoff);
    uint4 u[4];
    #pragma unroll
    for (int k = 0; k < 4; k++) u[k] = __ldcs(mv + tid + k * 512);

    // Fire-and-forget streaming zero write of the output row
    float4* out4 = (float4*)(out + rowoff);
    const float4 z4 = make_float4(0.f, 0.f, 0.f, 0.f);
    #pragma unroll
    for (int k = 0; k < 4; k++) __stcs(out4 + tid + k * 512, z4);

    __syncthreads();   // cnt/rowsum/x1s visible

    // --- Phase A: compaction ----------------------------------------------
    #pragma unroll
    for (int k = 0; k < 4; k++) {
        if (u[k].x | u[k].y | u[k].z | u[k].w) {
            int bj = (tid + k * 512) * 4;
            if (u[k].x) { int p = atomicAdd(&cnt, 1); idxs[p] = bj;     }
            if (u[k].y) { int p = atomicAdd(&cnt, 1); idxs[p] = bj + 1; }
            if (u[k].z) { int p = atomicAdd(&cnt, 1); idxs[p] = bj + 2; }
            if (u[k].w) { int p = atomicAdd(&cnt, 1); idxs[p] = bj + 3; }
        }
    }
    __syncthreads();
    const int m = cnt;

    // --- Phase B: half-warp per element ------------------------------------
    const int half = lane >> 4;                       // 0 or 1
    const int hl   = lane & 15;
    const unsigned hmask = 0xFFFFu << (half * 16);
    const float4 x1v = *(const float4*)(x1s + hl * 4);
    float lsum = 0.f;

    for (int el = wid * 2 + half; el < m; el += 32) {
        const int j = idxs[el];
        const float bb = __ldg(B + rowoff + j);       // half-warp broadcast
        const float vv = __ldg(V + rowoff + j);
        const float4 xv = __ldg((const float4*)(g_X2 + (size_t)j * CC) + hl);
        float p = xv.x * x1v.x + xv.y * x1v.y + xv.z * x1v.z + xv.w * x1v.w;
        #pragma unroll
        for (int o = 8; o; o >>= 1) p += __shfl_xor_sync(hmask, p, o);
        if (hl == 0) {
            const float sg = 1.f / (1.f + expf(-(p + bb)));
            const float ev = expf(vv * sg);
            e_c[el] = ev;
            lsum += ev;
        }
    }

    // --- Row sum: warp reduce + one smem atomic per warp --------------------
    #pragma unroll
    for (int o = 16; o; o >>= 1) lsum += __shfl_down_sync(0xffffffffu, lsum, o);
    if (lane == 0 && lsum != 0.f) atomicAdd(&rowsum, lsum);
    __syncthreads();

    // --- Sparse scatter of scaled values over the zeros ---------------------
    const float inv = 1.f / rowsum;
    for (int el = tid; el < m; el += 512)
        __stcs(out + rowoff + idxs[el], e_c[el] * inv);
}

extern "C" void kernel_launch(void* const* d_in, const int* in_sizes, int n_in,
                              void* d_out, int out_size)
{
    (void)in_sizes; (void)n_in; (void)out_size;
    const float* Hp  = (const float*)d_in[0];
    const float* w1  = (const float*)d_in[1];
    const float* W2  = (const float*)d_in[2];
    const float* w3  = (const float*)d_in[3];
    const float* V   = (const float*)d_in[4];
    const float* B   = (const float*)d_in[5];
    const unsigned int* mask = (const unsigned int*)d_in[6];
    float* out = (float*)d_out;

    prep_kernel<<<NS / 2, 256>>>(Hp, w1, W2, w3);
    row_kernel<<<NS, 512>>>(V, B, mask, out);
}